// round 1
// baseline (speedup 1.0000x reference)
#include <cuda_runtime.h>
#include <cuda_bf16.h>
#include <math.h>

// Problem constants (fixed by setup_inputs)
#define NQ    8
#define BINS  1024
#define DIM   256
#define BB    16
#define TT    1500
#define NN    (BB * TT)          // 24000 residual vectors
#define NPAD  24064              // 188 * 128
#define NBLK  (NPAD / 128)       // 188

// Scratch (device globals; no allocation allowed)
__device__ float g_res[NPAD * DIM];      // residual, (N,D) row-major
__device__ float g_acc[NPAD * DIM];      // accumulated quantized output, (N,D)
__device__ int   g_idx[NPAD];            // per-row argmax code
__device__ float g_cbsq[NQ * BINS];      // ||c||^2 per code
__device__ float g_partial[NQ * NN];     // per-(q,row) loss partial sums

// ---------------------------------------------------------------------------
// init: residual[n,d] = x[b,d,t] with n = b*T + t; accum = 0
// ---------------------------------------------------------------------------
__global__ void rvq_init(const float* __restrict__ x) {
    long long i = (long long)blockIdx.x * blockDim.x + threadIdx.x;
    long long total = (long long)NPAD * DIM;
    for (; i < total; i += (long long)gridDim.x * blockDim.x) {
        int n = (int)(i / DIM);
        int d = (int)(i - (long long)n * DIM);
        float v = 0.0f;
        if (n < NN) {
            int b = n / TT;
            int t = n - b * TT;
            v = x[(long long)b * DIM * TT + (long long)d * TT + t];
        }
        g_res[i] = v;
        g_acc[i] = 0.0f;
    }
}

// ---------------------------------------------------------------------------
// cbsq: one warp per (q,k) row, reduce 256 squares
// ---------------------------------------------------------------------------
__global__ void rvq_cbsq(const float* __restrict__ cb) {
    int warp = (blockIdx.x * blockDim.x + threadIdx.x) >> 5;
    int lane = threadIdx.x & 31;
    if (warp >= NQ * BINS) return;
    const float* row = cb + (long long)warp * DIM;
    float s = 0.0f;
    #pragma unroll
    for (int d = lane; d < DIM; d += 32) {
        float c = row[d];
        s += c * c;
    }
    #pragma unroll
    for (int off = 16; off > 0; off >>= 1)
        s += __shfl_down_sync(0xffffffffu, s, off);
    if (lane == 0) g_cbsq[warp] = s;
}

// ---------------------------------------------------------------------------
// argmax GEMM: per block of 128 residual rows, scan all 1024 codes.
// score[n,k] = 2 * <r_n, c_k> - ||c_k||^2 ; keep argmax (ties -> smallest k).
// 128x128 tile, 8x8 microtile, DK=16 smem tiles over D=256.
// ---------------------------------------------------------------------------
__global__ __launch_bounds__(256, 2)
void rvq_argmax(const float* __restrict__ cb, int q) {
    __shared__ float As[16][128];
    __shared__ float Bs[16][128];

    const int tid = threadIdx.x;
    const int tx  = tid & 15;
    const int ty  = tid >> 4;
    const int blockRow = blockIdx.x * 128;

    // global tile load mapping: 128 rows x 16 cols = 512 float4; 2 per thread
    const int lr = tid >> 2;       // 0..63
    const int lp = tid & 3;        // 0..3 (float4 slot within the 16-col row)

    const float* __restrict__ cbsq = g_cbsq + q * BINS;

    float best[8];
    int   bidx[8];
    #pragma unroll
    for (int i = 0; i < 8; i++) { best[i] = -3.402823466e+38f; bidx[i] = 0; }

    for (int kt = 0; kt < 8; kt++) {
        float acc[8][8];
        #pragma unroll
        for (int i = 0; i < 8; i++)
            #pragma unroll
            for (int j = 0; j < 8; j++)
                acc[i][j] = 0.0f;

        const float* __restrict__ cbt = cb + (long long)(kt * 128) * DIM;

        for (int dt = 0; dt < 16; dt++) {
            const int d0 = dt * 16;
            __syncthreads();
            // load A tile (residual rows)
            {
                float4 a0 = *(const float4*)&g_res[(long long)(blockRow + lr) * DIM + d0 + lp * 4];
                float4 a1 = *(const float4*)&g_res[(long long)(blockRow + lr + 64) * DIM + d0 + lp * 4];
                As[lp * 4 + 0][lr] = a0.x; As[lp * 4 + 1][lr] = a0.y;
                As[lp * 4 + 2][lr] = a0.z; As[lp * 4 + 3][lr] = a0.w;
                As[lp * 4 + 0][lr + 64] = a1.x; As[lp * 4 + 1][lr + 64] = a1.y;
                As[lp * 4 + 2][lr + 64] = a1.z; As[lp * 4 + 3][lr + 64] = a1.w;
            }
            // load B tile (codebook rows)
            {
                float4 b0 = *(const float4*)&cbt[(long long)lr * DIM + d0 + lp * 4];
                float4 b1 = *(const float4*)&cbt[(long long)(lr + 64) * DIM + d0 + lp * 4];
                Bs[lp * 4 + 0][lr] = b0.x; Bs[lp * 4 + 1][lr] = b0.y;
                Bs[lp * 4 + 2][lr] = b0.z; Bs[lp * 4 + 3][lr] = b0.w;
                Bs[lp * 4 + 0][lr + 64] = b1.x; Bs[lp * 4 + 1][lr + 64] = b1.y;
                Bs[lp * 4 + 2][lr + 64] = b1.z; Bs[lp * 4 + 3][lr + 64] = b1.w;
            }
            __syncthreads();

            #pragma unroll
            for (int kk = 0; kk < 16; kk++) {
                float a[8], b[8];
                #pragma unroll
                for (int u = 0; u < 4; u++) {
                    a[u]     = As[kk][ty * 4 + u];
                    a[4 + u] = As[kk][64 + ty * 4 + u];
                    b[u]     = Bs[kk][tx * 4 + u];
                    b[4 + u] = Bs[kk][64 + tx * 4 + u];
                }
                #pragma unroll
                for (int i = 0; i < 8; i++)
                    #pragma unroll
                    for (int j = 0; j < 8; j++)
                        acc[i][j] = fmaf(a[i], b[j], acc[i][j]);
            }
        }

        // fold this K-tile into the running argmax
        #pragma unroll
        for (int j = 0; j < 8; j++) {
            int col = (j < 4) ? (tx * 4 + j) : (64 + tx * 4 + (j - 4));
            int k   = kt * 128 + col;
            float csq = cbsq[k];
            #pragma unroll
            for (int i = 0; i < 8; i++) {
                float s = 2.0f * acc[i][j] - csq;
                if (s > best[i] || (s == best[i] && k < bidx[i])) {
                    best[i] = s;
                    bidx[i] = k;
                }
            }
        }
    }

    // cross-thread argmax reduction (16 tx slices per row), reuse smem
    __syncthreads();
    float* sS = &As[0][0];               // 128 x 16 floats
    int*   sI = (int*)&Bs[0][0];         // 128 x 16 ints
    #pragma unroll
    for (int i = 0; i < 8; i++) {
        int row = (i < 4) ? (ty * 4 + i) : (64 + ty * 4 + (i - 4));
        sS[row * 16 + tx] = best[i];
        sI[row * 16 + tx] = bidx[i];
    }
    __syncthreads();
    if (tid < 128) {
        float bs = -3.402823466e+38f;
        int   bi = 0x7fffffff;
        #pragma unroll
        for (int t = 0; t < 16; t++) {
            float s = sS[tid * 16 + t];
            int   k = sI[tid * 16 + t];
            if (s > bs || (s == bs && k < bi)) { bs = s; bi = k; }
        }
        g_idx[blockRow + tid] = bi;
    }
}

// ---------------------------------------------------------------------------
// update: quant = cb[idx]; residual -= quant; accum += quant;
// per-row loss partial = sum_d (residual_new)^2 (deterministic, no atomics)
// ---------------------------------------------------------------------------
__global__ void rvq_update(const float* __restrict__ cb, float* __restrict__ codes_out, int q) {
    __shared__ float red[8];
    const int n = blockIdx.x;           // 0..NN-1
    const int d = threadIdx.x;          // 0..255
    const int k = g_idx[n];

    float qv = cb[(long long)k * DIM + d];
    long long off = (long long)n * DIM + d;
    float r  = g_res[off];
    float rn = r - qv;
    g_res[off] = rn;
    g_acc[off] += qv;

    float sq = rn * rn;
    #pragma unroll
    for (int o = 16; o > 0; o >>= 1)
        sq += __shfl_down_sync(0xffffffffu, sq, o);
    if ((d & 31) == 0) red[d >> 5] = sq;
    __syncthreads();
    if (d == 0) {
        float tot = 0.0f;
        #pragma unroll
        for (int w = 0; w < 8; w++) tot += red[w];
        g_partial[q * NN + n] = tot;
        codes_out[q * NN + n] = (float)k;
    }
}

// ---------------------------------------------------------------------------
// finalize: quantized[b,d,t] = accum[b*T+t, d]  (transpose back)
// ---------------------------------------------------------------------------
__global__ void rvq_finalize(float* __restrict__ out) {
    long long i = (long long)blockIdx.x * blockDim.x + threadIdx.x;
    long long total = (long long)BB * DIM * TT;
    for (; i < total; i += (long long)gridDim.x * blockDim.x) {
        int b   = (int)(i / ((long long)DIM * TT));
        long long rem = i - (long long)b * DIM * TT;
        int d   = (int)(rem / TT);
        int t   = (int)(rem - (long long)d * TT);
        out[i] = g_acc[(long long)(b * TT + t) * DIM + d];
    }
}

// ---------------------------------------------------------------------------
// penalty: mean over all 8 losses; each loss is mean over N*D elements
// ---------------------------------------------------------------------------
__global__ void rvq_penalty(float* __restrict__ out) {
    __shared__ float red[8];
    const int tid = threadIdx.x;   // 256 threads, 1 block
    float s = 0.0f;
    for (int i = tid; i < NQ * NN; i += 256) s += g_partial[i];
    #pragma unroll
    for (int o = 16; o > 0; o >>= 1)
        s += __shfl_down_sync(0xffffffffu, s, o);
    if ((tid & 31) == 0) red[tid >> 5] = s;
    __syncthreads();
    if (tid == 0) {
        float tot = 0.0f;
        #pragma unroll
        for (int w = 0; w < 8; w++) tot += red[w];
        out[(long long)BB * DIM * TT + (long long)NQ * NN] =
            tot / ((float)NQ * (float)NN * (float)DIM);
    }
}

// ---------------------------------------------------------------------------
// launch
// ---------------------------------------------------------------------------
extern "C" void kernel_launch(void* const* d_in, const int* in_sizes, int n_in,
                              void* d_out, int out_size) {
    const float* x   = (const float*)d_in[0];   // (B, D, T) float32
    const float* cbs = (const float*)d_in[1];   // (NQ, BINS, D) float32
    float* out = (float*)d_out;                 // [quantized | codes | penalty]

    float* codes_out = out + (long long)BB * DIM * TT;

    rvq_init<<<2048, 256>>>(x);
    rvq_cbsq<<<(NQ * BINS * 32 + 255) / 256, 256>>>(cbs);

    for (int q = 0; q < NQ; q++) {
        const float* cb = cbs + (long long)q * BINS * DIM;
        rvq_argmax<<<NBLK, 256>>>(cb, q);
        rvq_update<<<NN, 256>>>(cb, codes_out, q);
    }

    rvq_finalize<<<2048, 256>>>(out);
    rvq_penalty<<<1, 256>>>(out);
}

// round 2
// speedup vs baseline: 1.0020x; 1.0020x over previous
#include <cuda_runtime.h>
#include <cuda_bf16.h>
#include <math.h>

// Problem constants (fixed by setup_inputs)
#define NQ    8
#define BINS  1024
#define DIM   256
#define BB    16
#define TT    1500
#define NN    (BB * TT)          // 24000 residual vectors
#define NPAD  24064              // 188 * 128
#define NBLK  (NPAD / 128)       // 188

// Scratch (device globals; no allocation allowed)
__device__ float g_res[NPAD * DIM];      // residual, (N,D) row-major
__device__ float g_acc[NPAD * DIM];      // accumulated quantized output, (N,D)
__device__ int   g_idx[NPAD];            // per-row argmax code
__device__ float g_cbsq[NQ * BINS];      // ||c||^2 per code
__device__ float g_partial[NQ * NN];     // per-(q,row) loss partial sums

// ---------------------------------------------------------------------------
// init: residual[n,d] = x[b,d,t] with n = b*T + t; accum = 0
// ---------------------------------------------------------------------------
__global__ void rvq_init(const float* __restrict__ x) {
    long long i = (long long)blockIdx.x * blockDim.x + threadIdx.x;
    long long total = (long long)NPAD * DIM;
    for (; i < total; i += (long long)gridDim.x * blockDim.x) {
        int n = (int)(i / DIM);
        int d = (int)(i - (long long)n * DIM);
        float v = 0.0f;
        if (n < NN) {
            int b = n / TT;
            int t = n - b * TT;
            v = x[(long long)b * DIM * TT + (long long)d * TT + t];
        }
        g_res[i] = v;
        g_acc[i] = 0.0f;
    }
}

// ---------------------------------------------------------------------------
// cbsq: one warp per (q,k) row, reduce 256 squares
// ---------------------------------------------------------------------------
__global__ void rvq_cbsq(const float* __restrict__ cb) {
    int warp = (blockIdx.x * blockDim.x + threadIdx.x) >> 5;
    int lane = threadIdx.x & 31;
    if (warp >= NQ * BINS) return;
    const float* row = cb + (long long)warp * DIM;
    float s = 0.0f;
    #pragma unroll
    for (int d = lane; d < DIM; d += 32) {
        float c = row[d];
        s += c * c;
    }
    #pragma unroll
    for (int off = 16; off > 0; off >>= 1)
        s += __shfl_down_sync(0xffffffffu, s, off);
    if (lane == 0) g_cbsq[warp] = s;
}

// ---------------------------------------------------------------------------
// argmax GEMM: per block of 128 residual rows, scan all 1024 codes.
// score[n,k] = 2 * <r_n, c_k> - ||c_k||^2 ; keep argmax (ties -> smallest k).
// 128x128 tile, 8x8 microtile, DK=16 smem tiles over D=256.
// ---------------------------------------------------------------------------
__global__ __launch_bounds__(256, 2)
void rvq_argmax(const float* __restrict__ cb, int q) {
    __shared__ float As[16][128];
    __shared__ float Bs[16][128];

    const int tid = threadIdx.x;
    const int tx  = tid & 15;
    const int ty  = tid >> 4;
    const int blockRow = blockIdx.x * 128;

    // global tile load mapping: 128 rows x 16 cols = 512 float4; 2 per thread
    const int lr = tid >> 2;       // 0..63
    const int lp = tid & 3;        // 0..3 (float4 slot within the 16-col row)

    const float* __restrict__ cbsq = g_cbsq + q * BINS;

    float best[8];
    int   bidx[8];
    #pragma unroll
    for (int i = 0; i < 8; i++) { best[i] = -3.402823466e+38f; bidx[i] = 0; }

    for (int kt = 0; kt < 8; kt++) {
        float acc[8][8];
        #pragma unroll
        for (int i = 0; i < 8; i++)
            #pragma unroll
            for (int j = 0; j < 8; j++)
                acc[i][j] = 0.0f;

        const float* __restrict__ cbt = cb + (long long)(kt * 128) * DIM;

        for (int dt = 0; dt < 16; dt++) {
            const int d0 = dt * 16;
            __syncthreads();
            // load A tile (residual rows)
            {
                float4 a0 = *(const float4*)&g_res[(long long)(blockRow + lr) * DIM + d0 + lp * 4];
                float4 a1 = *(const float4*)&g_res[(long long)(blockRow + lr + 64) * DIM + d0 + lp * 4];
                As[lp * 4 + 0][lr] = a0.x; As[lp * 4 + 1][lr] = a0.y;
                As[lp * 4 + 2][lr] = a0.z; As[lp * 4 + 3][lr] = a0.w;
                As[lp * 4 + 0][lr + 64] = a1.x; As[lp * 4 + 1][lr + 64] = a1.y;
                As[lp * 4 + 2][lr + 64] = a1.z; As[lp * 4 + 3][lr + 64] = a1.w;
            }
            // load B tile (codebook rows)
            {
                float4 b0 = *(const float4*)&cbt[(long long)lr * DIM + d0 + lp * 4];
                float4 b1 = *(const float4*)&cbt[(long long)(lr + 64) * DIM + d0 + lp * 4];
                Bs[lp * 4 + 0][lr] = b0.x; Bs[lp * 4 + 1][lr] = b0.y;
                Bs[lp * 4 + 2][lr] = b0.z; Bs[lp * 4 + 3][lr] = b0.w;
                Bs[lp * 4 + 0][lr + 64] = b1.x; Bs[lp * 4 + 1][lr + 64] = b1.y;
                Bs[lp * 4 + 2][lr + 64] = b1.z; Bs[lp * 4 + 3][lr + 64] = b1.w;
            }
            __syncthreads();

            #pragma unroll
            for (int kk = 0; kk < 16; kk++) {
                float a[8], b[8];
                #pragma unroll
                for (int u = 0; u < 4; u++) {
                    a[u]     = As[kk][ty * 4 + u];
                    a[4 + u] = As[kk][64 + ty * 4 + u];
                    b[u]     = Bs[kk][tx * 4 + u];
                    b[4 + u] = Bs[kk][64 + tx * 4 + u];
                }
                #pragma unroll
                for (int i = 0; i < 8; i++)
                    #pragma unroll
                    for (int j = 0; j < 8; j++)
                        acc[i][j] = fmaf(a[i], b[j], acc[i][j]);
            }
        }

        // fold this K-tile into the running argmax
        #pragma unroll
        for (int j = 0; j < 8; j++) {
            int col = (j < 4) ? (tx * 4 + j) : (64 + tx * 4 + (j - 4));
            int k   = kt * 128 + col;
            float csq = cbsq[k];
            #pragma unroll
            for (int i = 0; i < 8; i++) {
                float s = 2.0f * acc[i][j] - csq;
                if (s > best[i] || (s == best[i] && k < bidx[i])) {
                    best[i] = s;
                    bidx[i] = k;
                }
            }
        }
    }

    // cross-thread argmax reduction (16 tx slices per row), reuse smem
    __syncthreads();
    float* sS = &As[0][0];               // 128 x 16 floats
    int*   sI = (int*)&Bs[0][0];         // 128 x 16 ints
    #pragma unroll
    for (int i = 0; i < 8; i++) {
        int row = (i < 4) ? (ty * 4 + i) : (64 + ty * 4 + (i - 4));
        sS[row * 16 + tx] = best[i];
        sI[row * 16 + tx] = bidx[i];
    }
    __syncthreads();
    if (tid < 128) {
        float bs = -3.402823466e+38f;
        int   bi = 0x7fffffff;
        #pragma unroll
        for (int t = 0; t < 16; t++) {
            float s = sS[tid * 16 + t];
            int   k = sI[tid * 16 + t];
            if (s > bs || (s == bs && k < bi)) { bs = s; bi = k; }
        }
        g_idx[blockRow + tid] = bi;
    }
}

// ---------------------------------------------------------------------------
// update: quant = cb[idx]; residual -= quant; accum += quant;
// per-row loss partial = sum_d (residual_new)^2 (deterministic, no atomics)
// ---------------------------------------------------------------------------
__global__ void rvq_update(const float* __restrict__ cb, float* __restrict__ codes_out, int q) {
    __shared__ float red[8];
    const int n = blockIdx.x;           // 0..NN-1
    const int d = threadIdx.x;          // 0..255
    const int k = g_idx[n];

    float qv = cb[(long long)k * DIM + d];
    long long off = (long long)n * DIM + d;
    float r  = g_res[off];
    float rn = r - qv;
    g_res[off] = rn;
    g_acc[off] += qv;

    float sq = rn * rn;
    #pragma unroll
    for (int o = 16; o > 0; o >>= 1)
        sq += __shfl_down_sync(0xffffffffu, sq, o);
    if ((d & 31) == 0) red[d >> 5] = sq;
    __syncthreads();
    if (d == 0) {
        float tot = 0.0f;
        #pragma unroll
        for (int w = 0; w < 8; w++) tot += red[w];
        g_partial[q * NN + n] = tot;
        codes_out[q * NN + n] = (float)k;
    }
}

// ---------------------------------------------------------------------------
// finalize: quantized[b,d,t] = accum[b*T+t, d]  (transpose back)
// ---------------------------------------------------------------------------
__global__ void rvq_finalize(float* __restrict__ out) {
    long long i = (long long)blockIdx.x * blockDim.x + threadIdx.x;
    long long total = (long long)BB * DIM * TT;
    for (; i < total; i += (long long)gridDim.x * blockDim.x) {
        int b   = (int)(i / ((long long)DIM * TT));
        long long rem = i - (long long)b * DIM * TT;
        int d   = (int)(rem / TT);
        int t   = (int)(rem - (long long)d * TT);
        out[i] = g_acc[(long long)(b * TT + t) * DIM + d];
    }
}

// ---------------------------------------------------------------------------
// penalty: mean over all 8 losses; each loss is mean over N*D elements
// ---------------------------------------------------------------------------
__global__ void rvq_penalty(float* __restrict__ out) {
    __shared__ float red[8];
    const int tid = threadIdx.x;   // 256 threads, 1 block
    float s = 0.0f;
    for (int i = tid; i < NQ * NN; i += 256) s += g_partial[i];
    #pragma unroll
    for (int o = 16; o > 0; o >>= 1)
        s += __shfl_down_sync(0xffffffffu, s, o);
    if ((tid & 31) == 0) red[tid >> 5] = s;
    __syncthreads();
    if (tid == 0) {
        float tot = 0.0f;
        #pragma unroll
        for (int w = 0; w < 8; w++) tot += red[w];
        out[(long long)BB * DIM * TT + (long long)NQ * NN] =
            tot / ((float)NQ * (float)NN * (float)DIM);
    }
}

// ---------------------------------------------------------------------------
// launch
// ---------------------------------------------------------------------------
extern "C" void kernel_launch(void* const* d_in, const int* in_sizes, int n_in,
                              void* d_out, int out_size) {
    const float* x   = (const float*)d_in[0];   // (B, D, T) float32
    const float* cbs = (const float*)d_in[1];   // (NQ, BINS, D) float32
    float* out = (float*)d_out;                 // [quantized | codes | penalty]

    float* codes_out = out + (long long)BB * DIM * TT;

    rvq_init<<<2048, 256>>>(x);
    rvq_cbsq<<<(NQ * BINS * 32 + 255) / 256, 256>>>(cbs);

    for (int q = 0; q < NQ; q++) {
        const float* cb = cbs + (long long)q * BINS * DIM;
        rvq_argmax<<<NBLK, 256>>>(cb, q);
        rvq_update<<<NN, 256>>>(cb, codes_out, q);
    }

    rvq_finalize<<<2048, 256>>>(out);
    rvq_penalty<<<1, 256>>>(out);
}

// round 4
// speedup vs baseline: 1.7507x; 1.7473x over previous
#include <cuda_runtime.h>
#include <cuda_bf16.h>
#include <cstdint>
#include <float.h>

#define NQ    8
#define BINS  1024
#define DIM   256
#define BB    16
#define TT    1500
#define NN    (BB * TT)
#define NPAD  24064
#define NTILE 188

// device scratch
__device__ float g_res[NPAD * DIM];
__device__ float g_acc[NPAD * DIM];
__device__ int   g_cand[NPAD * 8];
__device__ float g_cand_s[NPAD * 8];
__device__ float g_cbsq[NQ * BINS];
__device__ float g_partial[NQ * NN];

// ---------------- helpers ----------------
__device__ __forceinline__ uint32_t smem_u32(const void* p) {
    uint32_t a;
    asm("{ .reg .u64 t; cvta.to.shared.u64 t, %1; cvt.u32.u64 %0, t; }" : "=r"(a) : "l"(p));
    return a;
}
__device__ __forceinline__ void cp_async16(uint32_t dst, const void* src) {
    asm volatile("cp.async.cg.shared.global [%0], [%1], 16;" :: "r"(dst), "l"(src) : "memory");
}
#define CP_COMMIT() asm volatile("cp.async.commit_group;" ::: "memory")
#define CP_WAIT0()  asm volatile("cp.async.wait_group 0;" ::: "memory")
#define CP_WAIT1()  asm volatile("cp.async.wait_group 1;" ::: "memory")

__device__ __forceinline__ void mma_tf32(float* c, const uint32_t* a, const uint32_t* b) {
    asm volatile(
        "mma.sync.aligned.m16n8k8.row.col.f32.tf32.tf32.f32 "
        "{%0,%1,%2,%3}, {%4,%5,%6,%7}, {%8,%9}, {%0,%1,%2,%3};"
        : "+f"(c[0]), "+f"(c[1]), "+f"(c[2]), "+f"(c[3])
        : "r"(a[0]), "r"(a[1]), "r"(a[2]), "r"(a[3]), "r"(b[0]), "r"(b[1]));
}

// smem layout (floats), dynamic:
//   A[2][128][36]  (9216)   off 0
//   B[2][64][36]   (4608)   off 9216
//   sc[128][66]    (8448)   off 13824
//   cbsq[1024]     (1024)   off 22272
// total 23296 floats = 93184 bytes
#define SM_A(buf, r, c)  (((buf) * 128 + (r)) * 36 + (c))
#define SM_B(buf, r, c)  (9216 + ((buf) * 64 + (r)) * 36 + (c))
#define SM_SC(r, c)      (13824 + (r) * 66 + (c))
#define SM_CBSQ(i)       (22272 + (i))
#define SMEM_FLOATS      23296
#define SMEM_BYTES       (SMEM_FLOATS * 4)

// ---------------- init: x (B,D,T) -> g_res (N,D) ----------------
__global__ void rvq_init(const float* __restrict__ x) {
    __shared__ float s[32][33];
    int b = blockIdx.z, d0 = blockIdx.y * 32, t0 = blockIdx.x * 32;
    int tx = threadIdx.x, ty = threadIdx.y;
    int t = t0 + tx;
    if (t < TT) s[ty][tx] = x[((size_t)b * DIM + d0 + ty) * TT + t];
    __syncthreads();
    int t2 = t0 + ty;
    if (t2 < TT) g_res[((size_t)(b * TT + t2)) * DIM + d0 + tx] = s[tx][ty];
}

__global__ void rvq_zero() {
    size_t i = (size_t)blockIdx.x * blockDim.x + threadIdx.x;
    size_t tot = (size_t)NPAD * DIM;
    for (; i < tot; i += (size_t)gridDim.x * blockDim.x) {
        g_acc[i] = 0.0f;
        if (i >= (size_t)NN * DIM) g_res[i] = 0.0f;
    }
}

// ---------------- cbsq ----------------
__global__ void rvq_cbsq(const float* __restrict__ cb) {
    int warp = (blockIdx.x * blockDim.x + threadIdx.x) >> 5;
    int lane = threadIdx.x & 31;
    if (warp >= NQ * BINS) return;
    const float* row = cb + (size_t)warp * DIM;
    float s = 0.0f;
    for (int d = lane; d < DIM; d += 32) { float c = row[d]; s += c * c; }
    #pragma unroll
    for (int o = 16; o > 0; o >>= 1) s += __shfl_down_sync(0xffffffffu, s, o);
    if (lane == 0) g_cbsq[warp] = s;
}

// ---------------- tf32 tensor-core argmax: top-8 candidates per row ----------------
__global__ __launch_bounds__(256, 2) void rvq_argmax_tc(const float* __restrict__ cbs, int q) {
    extern __shared__ float sm[];
    const uint32_t sb = smem_u32(sm);
    const int tid = threadIdx.x;
    const int lane = tid & 31, wid = tid >> 5;
    const int gid = lane >> 2, tg = lane & 3;
    const int wm = wid & 3, wn = wid >> 2;     // warp grid 4 (m) x 2 (n)
    const int row0 = blockIdx.x * 128;
    const float* __restrict__ cb = cbs + (size_t)q * BINS * DIM;

    for (int i = tid; i < BINS; i += 256) sm[SM_CBSQ(i)] = g_cbsq[q * BINS + i];

    // cp.async unit mapping (16B units)
    const int ur = tid >> 3;        // base row step
    const int useg = tid & 7;       // 16B segment within 32-float row

    float ts[8]; int txi[8];
    #pragma unroll
    for (int j = 0; j < 8; j++) { ts[j] = -FLT_MAX; txi[j] = 0; }

    #pragma unroll 1
    for (int nt = 0; nt < 16; nt++) {
        float c[2][4][4];
        #pragma unroll
        for (int mi = 0; mi < 2; mi++)
            #pragma unroll
            for (int ni = 0; ni < 4; ni++)
                #pragma unroll
                for (int v = 0; v < 4; v++) c[mi][ni][v] = 0.0f;

        // prefetch kc=0 into buf 0
        {
            #pragma unroll
            for (int i = 0; i < 4; i++) {
                int r = ur + i * 32;
                cp_async16(sb + SM_A(0, r, useg * 4) * 4,
                           g_res + (size_t)(row0 + r) * DIM + useg * 4);
            }
            #pragma unroll
            for (int i = 0; i < 2; i++) {
                int r = ur + i * 32;
                if (r < 64)
                    cp_async16(sb + SM_B(0, r, useg * 4) * 4,
                               cb + (size_t)(nt * 64 + r) * DIM + useg * 4);
            }
            CP_COMMIT();
        }

        #pragma unroll 1
        for (int kc = 0; kc < 8; kc++) {
            if (kc < 7) {
                int nb = (kc + 1) & 1;
                int kof = (kc + 1) * 32;
                #pragma unroll
                for (int i = 0; i < 4; i++) {
                    int r = ur + i * 32;
                    cp_async16(sb + SM_A(nb, r, useg * 4) * 4,
                               g_res + (size_t)(row0 + r) * DIM + kof + useg * 4);
                }
                #pragma unroll
                for (int i = 0; i < 2; i++) {
                    int r = ur + i * 32;
                    if (r < 64)
                        cp_async16(sb + SM_B(nb, r, useg * 4) * 4,
                                   cb + (size_t)(nt * 64 + r) * DIM + kof + useg * 4);
                }
                CP_COMMIT();
                CP_WAIT1();
            } else {
                CP_WAIT0();
            }
            __syncthreads();

            const int buf = kc & 1;
            #pragma unroll
            for (int kk = 0; kk < 4; kk++) {
                const int k0 = kk * 8 + tg;
                uint32_t a[2][4], b[4][2];
                #pragma unroll
                for (int mi = 0; mi < 2; mi++) {
                    int r = wm * 32 + mi * 16 + gid;
                    a[mi][0] = __float_as_uint(sm[SM_A(buf, r,      k0)]);
                    a[mi][1] = __float_as_uint(sm[SM_A(buf, r + 8,  k0)]);
                    a[mi][2] = __float_as_uint(sm[SM_A(buf, r,      k0 + 4)]);
                    a[mi][3] = __float_as_uint(sm[SM_A(buf, r + 8,  k0 + 4)]);
                }
                #pragma unroll
                for (int ni = 0; ni < 4; ni++) {
                    int cn = wn * 32 + ni * 8 + gid;
                    b[ni][0] = __float_as_uint(sm[SM_B(buf, cn, k0)]);
                    b[ni][1] = __float_as_uint(sm[SM_B(buf, cn, k0 + 4)]);
                }
                #pragma unroll
                for (int mi = 0; mi < 2; mi++)
                    #pragma unroll
                    for (int ni = 0; ni < 4; ni++)
                        mma_tf32(c[mi][ni], a[mi], b[ni]);
            }
            __syncthreads();
        }

        // epilogue: accums -> score tile
        #pragma unroll
        for (int mi = 0; mi < 2; mi++)
            #pragma unroll
            for (int ni = 0; ni < 4; ni++) {
                int r  = wm * 32 + mi * 16 + gid;
                int cc = wn * 32 + ni * 8 + tg * 2;
                sm[SM_SC(r, cc)]     = c[mi][ni][0];
                sm[SM_SC(r, cc + 1)] = c[mi][ni][1];
                sm[SM_SC(r + 8, cc)]     = c[mi][ni][2];
                sm[SM_SC(r + 8, cc + 1)] = c[mi][ni][3];
            }
        __syncthreads();

        if (tid < 128) {
            #pragma unroll 4
            for (int cc = 0; cc < 64; cc++) {
                int k = nt * 64 + cc;
                float sc = 2.0f * sm[SM_SC(tid, cc)] - sm[SM_CBSQ(k)];
                if (sc > ts[7]) {
                    float cs = sc; int ci = k;
                    #pragma unroll
                    for (int j = 0; j < 8; j++) {
                        if (cs > ts[j]) {
                            float t0 = ts[j]; int t1 = txi[j];
                            ts[j] = cs; txi[j] = ci;
                            cs = t0; ci = t1;
                        }
                    }
                }
            }
        }
        __syncthreads();
    }

    if (tid < 128) {
        int row = row0 + tid;
        #pragma unroll
        for (int j = 0; j < 8; j++) {
            g_cand[row * 8 + j]   = txi[j];
            g_cand_s[row * 8 + j] = ts[j];
        }
    }
}

// ---------------- exact select (fp64, margin-filtered) + update, fused ----------------
__global__ void rvq_select_update(const float* __restrict__ cbs,
                                  float* __restrict__ codes_out, int q) {
    __shared__ double sS[8];
    __shared__ int sK;
    __shared__ float red[8];
    const int n = blockIdx.x, tid = threadIdx.x;
    const int w = tid >> 5, lane = tid & 31;
    const float* __restrict__ cb = cbs + (size_t)q * BINS * DIM;

    const int   cand = g_cand[n * 8 + w];
    const float sap  = g_cand_s[n * 8 + w];
    const float s0ap = g_cand_s[n * 8];

    double scv = -1e300;
    if (sap >= s0ap - 0.25f) {
        const float* r = g_res + (size_t)n * DIM;
        const float* c = cb + (size_t)cand * DIM;
        double dot = 0.0, sq = 0.0;
        #pragma unroll
        for (int d = lane; d < DIM; d += 32) {
            double rv = r[d], cv = c[d];
            dot += rv * cv;
            sq  += cv * cv;
        }
        #pragma unroll
        for (int o = 16; o > 0; o >>= 1) {
            dot += __shfl_down_sync(0xffffffffu, dot, o);
            sq  += __shfl_down_sync(0xffffffffu, sq, o);
        }
        scv = 2.0 * dot - sq;
    }
    if (lane == 0) sS[w] = scv;
    __syncthreads();
    if (tid == 0) {
        double best = -1e301; int bk = 1 << 30;
        #pragma unroll
        for (int j = 0; j < 8; j++) {
            int k = g_cand[n * 8 + j];
            double s = sS[j];
            if (s > best || (s == best && k < bk)) { best = s; bk = k; }
        }
        sK = bk;
    }
    __syncthreads();

    const int k = sK;
    const int d = tid;
    float qv = cb[(size_t)k * DIM + d];
    size_t off = (size_t)n * DIM + d;
    float rn = g_res[off] - qv;
    g_res[off] = rn;
    g_acc[off] += qv;

    float sq2 = rn * rn;
    #pragma unroll
    for (int o = 16; o > 0; o >>= 1) sq2 += __shfl_down_sync(0xffffffffu, sq2, o);
    if ((d & 31) == 0) red[d >> 5] = sq2;
    __syncthreads();
    if (d == 0) {
        float tot = 0.0f;
        #pragma unroll
        for (int ww = 0; ww < 8; ww++) tot += red[ww];
        g_partial[q * NN + n] = tot;
        codes_out[q * NN + n] = (float)k;
    }
}

// ---------------- finalize: g_acc (N,D) -> out (B,D,T) ----------------
__global__ void rvq_finalize(float* __restrict__ out) {
    __shared__ float s[32][33];
    int b = blockIdx.z, d0 = blockIdx.y * 32, t0 = blockIdx.x * 32;
    int tx = threadIdx.x, ty = threadIdx.y;
    int t = t0 + ty;
    if (t < TT) s[ty][tx] = g_acc[((size_t)(b * TT + t)) * DIM + d0 + tx];
    __syncthreads();
    int t2 = t0 + tx;
    if (t2 < TT) out[((size_t)b * DIM + d0 + ty) * TT + t2] = s[tx][ty];
}

// ---------------- penalty ----------------
__global__ void rvq_penalty(float* __restrict__ out) {
    __shared__ float red[8];
    const int tid = threadIdx.x;
    float s = 0.0f;
    for (int i = tid; i < NQ * NN; i += 256) s += g_partial[i];
    #pragma unroll
    for (int o = 16; o > 0; o >>= 1) s += __shfl_down_sync(0xffffffffu, s, o);
    if ((tid & 31) == 0) red[tid >> 5] = s;
    __syncthreads();
    if (tid == 0) {
        float tot = 0.0f;
        #pragma unroll
        for (int w = 0; w < 8; w++) tot += red[w];
        out[(size_t)BB * DIM * TT + (size_t)NQ * NN] =
            tot / ((float)NQ * (float)NN * (float)DIM);
    }
}

// ---------------- launch ----------------
extern "C" void kernel_launch(void* const* d_in, const int* in_sizes, int n_in,
                              void* d_out, int out_size) {
    const float* x   = (const float*)d_in[0];
    const float* cbs = (const float*)d_in[1];
    float* out = (float*)d_out;
    float* codes_out = out + (size_t)BB * DIM * TT;

    static int smem_set = 0;
    if (!smem_set) {
        cudaFuncSetAttribute(rvq_argmax_tc,
                             cudaFuncAttributeMaxDynamicSharedMemorySize, SMEM_BYTES);
        smem_set = 1;
    }

    dim3 tb(32, 32);
    rvq_init<<<dim3(47, 8, 16), tb>>>(x);
    rvq_zero<<<512, 256>>>();
    rvq_cbsq<<<1024, 256>>>(cbs);

    for (int q = 0; q < NQ; q++) {
        rvq_argmax_tc<<<NTILE, 256, SMEM_BYTES>>>(cbs, q);
        rvq_select_update<<<NN, 256>>>(cbs, codes_out, q);
    }

    rvq_finalize<<<dim3(47, 8, 16), tb>>>(out);
    rvq_penalty<<<1, 256>>>(out);
}

// round 5
// speedup vs baseline: 2.0107x; 1.1485x over previous
#include <cuda_runtime.h>
#include <cuda_bf16.h>
#include <cstdint>
#include <float.h>

#define NQ    8
#define BINS  1024
#define DIM   256
#define BB    16
#define TT    1500
#define NN    (BB * TT)
#define NPAD  24064
#define NTILE 188

// device scratch
__device__ float g_res[NPAD * DIM];          // residual, D-permuted within 8-groups
__device__ float g_acc[NPAD * DIM];          // natural D order
__device__ float g_cbp[NQ * BINS * DIM];     // permuted codebook copy
__device__ int   g_cand[NPAD * 32];
__device__ float g_cand_s[NPAD * 32];
__device__ float g_cbsq[NQ * BINS];
__device__ float g_partial[NQ * NN];

// D permutation within each 8-group: orig o -> pos (o&~7)|((o&3)<<1)|((o&4)>>2)
__device__ __forceinline__ int permD(int o) { return (o & ~7) | ((o & 3) << 1) | ((o & 4) >> 2); }
__device__ __forceinline__ int invD(int p)  { return (p & ~7) | ((p & 1) << 2) | ((p & 6) >> 1); }

// ---------------- helpers ----------------
__device__ __forceinline__ uint32_t smem_u32(const void* p) {
    uint32_t a;
    asm("{ .reg .u64 t; cvta.to.shared.u64 t, %1; cvt.u32.u64 %0, t; }" : "=r"(a) : "l"(p));
    return a;
}
__device__ __forceinline__ void cp_async16(uint32_t dst, const void* src) {
    asm volatile("cp.async.cg.shared.global [%0], [%1], 16;" :: "r"(dst), "l"(src) : "memory");
}
#define CP_COMMIT() asm volatile("cp.async.commit_group;" ::: "memory")
#define CP_WAIT0()  asm volatile("cp.async.wait_group 0;" ::: "memory")
#define CP_WAIT1()  asm volatile("cp.async.wait_group 1;" ::: "memory")

__device__ __forceinline__ void mma_tf32(float* c, const uint32_t* a, const uint32_t* b) {
    asm volatile(
        "mma.sync.aligned.m16n8k8.row.col.f32.tf32.tf32.f32 "
        "{%0,%1,%2,%3}, {%4,%5,%6,%7}, {%8,%9}, {%0,%1,%2,%3};"
        : "+f"(c[0]), "+f"(c[1]), "+f"(c[2]), "+f"(c[3])
        : "r"(a[0]), "r"(a[1]), "r"(a[2]), "r"(a[3]), "r"(b[0]), "r"(b[1]));
}

// smem floats: A[2][128][32] @0 (8192), B[2][64][32] @8192 (4096), cbsq[512] @12288
#define SA(buf, r, c)  (((buf) * 128 + (r)) * 32 + (c))
#define SB(buf, r, c)  (8192 + ((buf) * 64 + (r)) * 32 + (c))
#define SQ(i)          (12288 + (i))
#define SMEM_BYTES     (12800 * 4)

// ---------------- init: x (B,D,T) -> g_res (N, permD) ----------------
__global__ void rvq_init(const float* __restrict__ x) {
    __shared__ float s[32][33];
    int b = blockIdx.z, d0 = blockIdx.y * 32, t0 = blockIdx.x * 32;
    int tx = threadIdx.x, ty = threadIdx.y;
    int t = t0 + tx;
    if (t < TT) s[ty][tx] = x[((size_t)b * DIM + d0 + ty) * TT + t];
    __syncthreads();
    int t2 = t0 + ty;
    if (t2 < TT)
        g_res[((size_t)(b * TT + t2)) * DIM + d0 + permD(tx)] = s[tx][ty];
}

__global__ void rvq_zero() {
    size_t i = (size_t)blockIdx.x * blockDim.x + threadIdx.x;
    size_t tot = (size_t)NPAD * DIM;
    for (; i < tot; i += (size_t)gridDim.x * blockDim.x) {
        g_acc[i] = 0.0f;
        if (i >= (size_t)NN * DIM) g_res[i] = 0.0f;
    }
}

// ---------------- cbsq + permuted codebook copy ----------------
__global__ void rvq_cbsq(const float* __restrict__ cb) {
    int warp = (blockIdx.x * blockDim.x + threadIdx.x) >> 5;
    int lane = threadIdx.x & 31;
    if (warp >= NQ * BINS) return;
    const float* row = cb + (size_t)warp * DIM;
    float s = 0.0f;
    for (int d = lane; d < DIM; d += 32) { float c = row[d]; s += c * c; }
    #pragma unroll
    for (int o = 16; o > 0; o >>= 1) s += __shfl_down_sync(0xffffffffu, s, o);
    if (lane == 0) g_cbsq[warp] = s;
}

__global__ void rvq_cbperm(const float* __restrict__ cbs) {
    size_t i = (size_t)blockIdx.x * blockDim.x + threadIdx.x;
    if (i >= (size_t)NQ * BINS * DIM) return;
    int d = (int)(i & 255);
    g_cbp[(i - d) + permD(d)] = cbs[i];
}

// ---------------- tf32 tensor-core argmax: half-tile = 128 rows x 512 bins ----------------
__global__ __launch_bounds__(256, 2) void rvq_argmax_tc(int q) {
    extern __shared__ float sm[];
    const uint32_t sb = smem_u32(sm);
    const int tid = threadIdx.x;
    const int lane = tid & 31, wid = tid >> 5;
    const int gid = lane >> 2, tg = lane & 3;
    const int wm = wid & 3, wn = wid >> 2;        // warp grid 4 (m) x 2 (n)
    const int mtile = blockIdx.x >> 1, half = blockIdx.x & 1;
    const int row0 = mtile * 128;
    const float* __restrict__ cbp = g_cbp + ((size_t)q * BINS + half * 512) * DIM;

    for (int i = tid; i < 512; i += 256) sm[SQ(i)] = g_cbsq[q * BINS + half * 512 + i];

    const int ur = tid >> 3, useg = tid & 7;

    float ts[4][2]; int ti[4][2];
    #pragma unroll
    for (int s = 0; s < 4; s++) {
        ts[s][0] = -FLT_MAX; ts[s][1] = -FLT_MAX;
        ti[s][0] = 0; ti[s][1] = 0;
    }

#define PREFETCH(bufv, kof, ntv) do { \
    _Pragma("unroll") \
    for (int i_ = 0; i_ < 4; i_++) { \
        int r_ = ur + i_ * 32; \
        cp_async16(sb + (uint32_t)SA(bufv, r_, (useg ^ (r_ & 7)) * 4) * 4u, \
                   g_res + (size_t)(row0 + r_) * DIM + (kof) + useg * 4); \
    } \
    _Pragma("unroll") \
    for (int i_ = 0; i_ < 2; i_++) { \
        int r_ = ur + i_ * 32; \
        cp_async16(sb + (uint32_t)SB(bufv, r_, (useg ^ (r_ & 7)) * 4) * 4u, \
                   cbp + (size_t)((ntv) * 64 + r_) * DIM + (kof) + useg * 4); \
    } \
    CP_COMMIT(); \
} while (0)

    #pragma unroll 1
    for (int nt = 0; nt < 8; nt++) {
        float c[2][4][4];
        #pragma unroll
        for (int mi = 0; mi < 2; mi++)
            #pragma unroll
            for (int ni = 0; ni < 4; ni++)
                #pragma unroll
                for (int v = 0; v < 4; v++) c[mi][ni][v] = 0.0f;

        PREFETCH(0, 0, nt);

        #pragma unroll 1
        for (int kc = 0; kc < 8; kc++) {
            if (kc < 7) {
                if ((kc & 1) == 0) PREFETCH(1, (kc + 1) * 32, nt);
                else               PREFETCH(0, (kc + 1) * 32, nt);
                CP_WAIT1();
            } else {
                CP_WAIT0();
            }
            __syncthreads();

            const int buf = kc & 1;
            #pragma unroll
            for (int kk = 0; kk < 4; kk++) {
                const int colp = (((2 * kk + (tg >> 1)) ^ gid) << 2) + 2 * (tg & 1);
                uint32_t a[2][4], b[4][2];
                #pragma unroll
                for (int mi = 0; mi < 2; mi++) {
                    int r = wm * 32 + mi * 16 + gid;
                    float2 av0 = *(const float2*)&sm[SA(buf, r, colp)];
                    float2 av1 = *(const float2*)&sm[SA(buf, r + 8, colp)];
                    a[mi][0] = __float_as_uint(av0.x);
                    a[mi][1] = __float_as_uint(av1.x);
                    a[mi][2] = __float_as_uint(av0.y);
                    a[mi][3] = __float_as_uint(av1.y);
                }
                #pragma unroll
                for (int ni = 0; ni < 4; ni++) {
                    int n = wn * 32 + ni * 8 + gid;
                    float2 bv = *(const float2*)&sm[SB(buf, n, colp)];
                    b[ni][0] = __float_as_uint(bv.x);
                    b[ni][1] = __float_as_uint(bv.y);
                }
                #pragma unroll
                for (int mi = 0; mi < 2; mi++)
                    #pragma unroll
                    for (int ni = 0; ni < 4; ni++)
                        mma_tf32(c[mi][ni], a[mi], b[ni]);
            }
            __syncthreads();
        }

        // register epilogue: fold scores into per-row top-2
#define FOLD(slot, sc, kg) do { \
    if ((sc) > ts[slot][0]) { \
        ts[slot][1] = ts[slot][0]; ti[slot][1] = ti[slot][0]; \
        ts[slot][0] = (sc); ti[slot][0] = (kg); \
    } else if ((sc) > ts[slot][1]) { ts[slot][1] = (sc); ti[slot][1] = (kg); } \
} while (0)

        #pragma unroll
        for (int mi = 0; mi < 2; mi++)
            #pragma unroll
            for (int ni = 0; ni < 4; ni++) {
                int cc = wn * 32 + ni * 8 + tg * 2;
                int kl = nt * 64 + cc;
                int kg = half * 512 + kl;
                float q0 = sm[SQ(kl)], q1 = sm[SQ(kl + 1)];
                float s0 = 2.0f * c[mi][ni][0] - q0;
                float s1 = 2.0f * c[mi][ni][1] - q1;
                float s2 = 2.0f * c[mi][ni][2] - q0;
                float s3 = 2.0f * c[mi][ni][3] - q1;
                FOLD(mi * 2 + 0, s0, kg);
                FOLD(mi * 2 + 0, s1, kg + 1);
                FOLD(mi * 2 + 1, s2, kg);
                FOLD(mi * 2 + 1, s3, kg + 1);
            }
    }

    // write 2 candidates per owned row
    const int owner = wn * 4 + tg;
    #pragma unroll
    for (int s = 0; s < 4; s++) {
        int row = row0 + wm * 32 + (s >> 1) * 16 + gid + (s & 1) * 8;
        size_t base = (size_t)row * 32 + half * 16 + owner * 2;
        g_cand[base]     = ti[s][0];  g_cand_s[base]     = ts[s][0];
        g_cand[base + 1] = ti[s][1];  g_cand_s[base + 1] = ts[s][1];
    }
}

// ---------------- exact select (fp64, margin-filtered) + update ----------------
__global__ void rvq_select_update(const float* __restrict__ cbs,
                                  float* __restrict__ codes_out, int q) {
    __shared__ float sApprox[32];
    __shared__ double sS[32];
    __shared__ int sK;
    __shared__ float red[8];
    __shared__ float sMax;
    const int n = blockIdx.x, tid = threadIdx.x;
    const int w = tid >> 5, lane = tid & 31;
    const float* __restrict__ cb = cbs + (size_t)q * BINS * DIM;

    if (tid < 32) {
        float a = g_cand_s[(size_t)n * 32 + tid];
        sApprox[tid] = a;
        sS[tid] = -1e300;
        #pragma unroll
        for (int o = 16; o > 0; o >>= 1) a = fmaxf(a, __shfl_down_sync(0xffffffffu, a, o));
        if (tid == 0) sMax = a;
    }
    __syncthreads();

    const float thr = sMax - 0.3f;
    #pragma unroll 1
    for (int c4 = 0; c4 < 4; c4++) {
        const int ci = w * 4 + c4;
        if (sApprox[ci] >= thr) {
            const int cand = g_cand[(size_t)n * 32 + ci];
            const float* r = g_res + (size_t)n * DIM;
            const float* c = cb + (size_t)cand * DIM;
            double dot = 0.0, sq = 0.0;
            #pragma unroll
            for (int d = lane; d < DIM; d += 32) {
                double rv = r[d], cv = c[invD(d)];
                dot += rv * cv; sq += cv * cv;
            }
            #pragma unroll
            for (int o = 16; o > 0; o >>= 1) {
                dot += __shfl_down_sync(0xffffffffu, dot, o);
                sq  += __shfl_down_sync(0xffffffffu, sq, o);
            }
            if (lane == 0) sS[ci] = 2.0 * dot - sq;
        }
    }
    __syncthreads();
    if (tid == 0) {
        double best = -1e301; int bk = 1 << 30;
        #pragma unroll
        for (int j = 0; j < 32; j++) {
            double s = sS[j];
            int k = g_cand[(size_t)n * 32 + j];
            if (s > best || (s == best && k < bk)) { best = s; bk = k; }
        }
        sK = bk;
    }
    __syncthreads();

    const int k = sK;
    const int od = invD(tid);
    const float qv = cb[(size_t)k * DIM + od];
    const size_t off = (size_t)n * DIM + tid;
    const float rn = g_res[off] - qv;
    g_res[off] = rn;
    g_acc[(size_t)n * DIM + od] += qv;

    float sq2 = rn * rn;
    #pragma unroll
    for (int o = 16; o > 0; o >>= 1) sq2 += __shfl_down_sync(0xffffffffu, sq2, o);
    if (lane == 0) red[w] = sq2;
    __syncthreads();
    if (tid == 0) {
        float tot = 0.0f;
        #pragma unroll
        for (int ww = 0; ww < 8; ww++) tot += red[ww];
        g_partial[q * NN + n] = tot;
        codes_out[q * NN + n] = (float)k;
    }
}

// ---------------- finalize: g_acc (N,D natural) -> out (B,D,T) ----------------
__global__ void rvq_finalize(float* __restrict__ out) {
    __shared__ float s[32][33];
    int b = blockIdx.z, d0 = blockIdx.y * 32, t0 = blockIdx.x * 32;
    int tx = threadIdx.x, ty = threadIdx.y;
    int t = t0 + ty;
    if (t < TT) s[ty][tx] = g_acc[((size_t)(b * TT + t)) * DIM + d0 + tx];
    __syncthreads();
    int t2 = t0 + tx;
    if (t2 < TT) out[((size_t)b * DIM + d0 + ty) * TT + t2] = s[tx][ty];
}

// ---------------- penalty ----------------
__global__ void rvq_penalty(float* __restrict__ out) {
    __shared__ float red[8];
    const int tid = threadIdx.x;
    float s = 0.0f;
    for (int i = tid; i < NQ * NN; i += 256) s += g_partial[i];
    #pragma unroll
    for (int o = 16; o > 0; o >>= 1) s += __shfl_down_sync(0xffffffffu, s, o);
    if ((tid & 31) == 0) red[tid >> 5] = s;
    __syncthreads();
    if (tid == 0) {
        float tot = 0.0f;
        #pragma unroll
        for (int w = 0; w < 8; w++) tot += red[w];
        out[(size_t)BB * DIM * TT + (size_t)NQ * NN] =
            tot / ((float)NQ * (float)NN * (float)DIM);
    }
}

// ---------------- launch ----------------
extern "C" void kernel_launch(void* const* d_in, const int* in_sizes, int n_in,
                              void* d_out, int out_size) {
    const float* x   = (const float*)d_in[0];
    const float* cbs = (const float*)d_in[1];
    float* out = (float*)d_out;
    float* codes_out = out + (size_t)BB * DIM * TT;

    cudaFuncSetAttribute(rvq_argmax_tc,
                         cudaFuncAttributeMaxDynamicSharedMemorySize, SMEM_BYTES);

    dim3 tb(32, 32);
    rvq_init<<<dim3(47, 8, 16), tb>>>(x);
    rvq_zero<<<512, 256>>>();
    rvq_cbsq<<<1024, 256>>>(cbs);
    rvq_cbperm<<<(NQ * BINS * DIM + 255) / 256, 256>>>(cbs);

    for (int q = 0; q < NQ; q++) {
        rvq_argmax_tc<<<NTILE * 2, 256, SMEM_BYTES>>>(q);
        rvq_select_update<<<NN, 256>>>(cbs, codes_out, q);
    }

    rvq_finalize<<<dim3(47, 8, 16), tb>>>(out);
    rvq_penalty<<<1, 256>>>(out);
}